// round 12
// baseline (speedup 1.0000x reference)
#include <cuda_runtime.h>

// entmax-1.5 attention, B=8, S=2048, D=128, fp32.
// One block = 16 query rows of one batch, 512 threads (16 warps).
//   1) QK: z[16][2048] = 0.5*Q K^T in SMEM via packed fma.rn.f32x2.
//      Q staged duplicated (q,q) so pairs load directly; K tile staged transposed
//      with coalesced LDG + XOR swizzle (identical to prior passing kernel).
//      Lane map qg=lane>>3, kq=lane&7: kv LDS dedups 4-way across q-groups.
//   2) bisection for tau: one warp per row, 64 z-values/thread in registers. 22 iters.
//   3) PV: O = w V, f32x2 pairs on V, (w,w) packs via mov.b64; 8-way k-split,
//      3-stage conflict-free SMEM tree reduction.

#define SLEN 2048
#define DDIM 128
#define TQ   16
#define ZSTR 2052   // z row stride (floats)
#define KSTR2 516   // transposed K tile row stride (floats), 512 k + pad
#define QDSTR 36    // duplicated-Q row stride (floats): 32 data + pad
#define NITER 22
#define NTHR 512

typedef unsigned long long ull;

__device__ __forceinline__ ull pack2(float v) {
    ull r;
    asm("mov.b64 %0, {%1, %1};" : "=l"(r) : "f"(v));
    return r;
}
__device__ __forceinline__ void fma2(ull& d, ull a, ull b) {
    asm("fma.rn.f32x2 %0, %1, %2, %0;" : "+l"(d) : "l"(a), "l"(b));
}
__device__ __forceinline__ void add4(float4& o, const float4& v) {
    o.x += v.x; o.y += v.y; o.z += v.z; o.w += v.w;
}

__global__ __launch_bounds__(NTHR, 1)
void entmax_attn_kernel(const float* __restrict__ Q,
                        const float* __restrict__ K,
                        const float* __restrict__ V,
                        float* __restrict__ O) {
    extern __shared__ float sm[];
    float* zsh = sm;                          // 16 * 2052 = 32,832 floats
    float* ks  = sm + TQ * ZSTR;              // 32 * 516  = 16,512 floats (reused: V stage / reduction)
    float* qd  = ks + 32 * KSTR2;             // 128 * 36  =  4,608 floats (duplicated Q)

    const int tid  = threadIdx.x;
    const int lane = tid & 31;
    const int warp = tid >> 5;
    const int b    = blockIdx.y;
    const int qt   = blockIdx.x;

    const float* Qb = Q + ((size_t)b * SLEN + qt * TQ) * DDIM;
    const float* Kb = K + (size_t)b * SLEN * DDIM;
    const float* Vb = V + (size_t)b * SLEN * DDIM;
    float*       Ob = O + ((size_t)b * SLEN + qt * TQ) * DDIM;

    // ---- stage Q tile transposed + duplicated: qd[d][2q]=qd[d][2q+1]=0.5*Q[q][d] ----
    {
        int q  = tid >> 5;       // 0..15 (== warp)
        int d4 = lane;           // 0..31
        float4 v = *(const float4*)(Qb + q * DDIM + d4 * 4);
        float vals[4] = {0.5f * v.x, 0.5f * v.y, 0.5f * v.z, 0.5f * v.w};
        #pragma unroll
        for (int c = 0; c < 4; c++) {
            qd[(d4 * 4 + c) * QDSTR + q * 2 + 0] = vals[c];
            qd[(d4 * 4 + c) * QDSTR + q * 2 + 1] = vals[c];
        }
    }

    // =========================== Phase 1: QK (f32x2) ===========================
    // Each warp: all 16 q rows x 32 k cols [warp*32, warp*32+32).
    // Lane: qg = lane>>3 (4 q rows qg*4..+3), kq = lane&7 (k chunk kq*4).
    const int qg  = lane >> 3;
    const int kg4 = warp * 32 + (lane & 7) * 4;
    // staging (unchanged from prior passing kernel): 8 lanes per K-row 128B slice
    const int d16  = (lane & 7) * 4;
    const int ksub = lane >> 3;

    for (int kb = 0; kb < SLEN; kb += 512) {
        ull acc[4][2];
        #pragma unroll
        for (int i = 0; i < 4; i++) { acc[i][0] = 0ull; acc[i][1] = 0ull; }

        for (int db = 0; db < DDIM; db += 32) {
            __syncthreads();
            #pragma unroll
            for (int r = 0; r < 8; r++) {
                int k = warp * 32 + r * 4 + ksub;           // contiguous 32 k per warp
                float4 v = *(const float4*)(Kb + (size_t)(kb + k) * DDIM + db + d16);
                int kx = k ^ d16;                            // swizzle within 32-k window
                ks[(d16 + 0) * KSTR2 + kx] = v.x;
                ks[(d16 + 1) * KSTR2 + kx] = v.y;
                ks[(d16 + 2) * KSTR2 + kx] = v.z;
                ks[(d16 + 3) * KSTR2 + kx] = v.w;
            }
            __syncthreads();
            #pragma unroll
            for (int dd = 0; dd < 32; dd++) {
                int f = dd & 0x1C;                           // 4*(dd>>2), warp-uniform
                const float* qp = qd + (db + dd) * QDSTR + qg * 8;
                ulonglong2 qa = *(const ulonglong2*)(qp);       // (q0,q0),(q1,q1)
                ulonglong2 qb2 = *(const ulonglong2*)(qp + 4);  // (q2,q2),(q3,q3)
                ulonglong2 kk = *(const ulonglong2*)(ks + dd * KSTR2 + (kg4 ^ f));
                fma2(acc[0][0], qa.x,  kk.x); fma2(acc[0][1], qa.x,  kk.y);
                fma2(acc[1][0], qa.y,  kk.x); fma2(acc[1][1], qa.y,  kk.y);
                fma2(acc[2][0], qb2.x, kk.x); fma2(acc[2][1], qb2.x, kk.y);
                fma2(acc[3][0], qb2.y, kk.x); fma2(acc[3][1], qb2.y, kk.y);
            }
        }
        #pragma unroll
        for (int i = 0; i < 4; i++) {
            ulonglong2 zz; zz.x = acc[i][0]; zz.y = acc[i][1];
            *(ulonglong2*)(zsh + (qg * 4 + i) * ZSTR + kb + kg4) = zz;
        }
    }
    __syncthreads();

    // =========================== Phase 2: bisection (one warp per row) ===========================
    {
        const int row = warp;      // 0..15
        float* zrow = zsh + row * ZSTR;

        float4 zr[16];
        #pragma unroll
        for (int j = 0; j < 16; j++)
            zr[j] = *(const float4*)(zrow + (j * 32 + lane) * 4);

        float m = zr[0].x;
        #pragma unroll
        for (int j = 0; j < 16; j++)
            m = fmaxf(m, fmaxf(fmaxf(zr[j].x, zr[j].y), fmaxf(zr[j].z, zr[j].w)));
        #pragma unroll
        for (int o = 16; o >= 1; o >>= 1)
            m = fmaxf(m, __shfl_xor_sync(0xffffffffu, m, o));

        float lo = m - 1.0f;
        float hi = m - 0.02209708691207961f;   // 2048^(1-1.5)
        float tau = 0.5f * (lo + hi);

        for (int it = 0; it < NITER; it++) {
            tau = 0.5f * (lo + hi);
            float s0 = 0.f, s1 = 0.f, s2 = 0.f, s3 = 0.f;
            #pragma unroll
            for (int j = 0; j < 16; j++) {
                float t0 = fmaxf(zr[j].x - tau, 0.f);
                float t1 = fmaxf(zr[j].y - tau, 0.f);
                float t2 = fmaxf(zr[j].z - tau, 0.f);
                float t3 = fmaxf(zr[j].w - tau, 0.f);
                s0 += t0 * t0; s1 += t1 * t1; s2 += t2 * t2; s3 += t3 * t3;
            }
            float s = (s0 + s1) + (s2 + s3);
            #pragma unroll
            for (int o = 16; o >= 1; o >>= 1)
                s += __shfl_xor_sync(0xffffffffu, s, o);
            if (s >= 1.0f) lo = tau; else hi = tau;
        }

        // final p, Z with last tau (matches reference)
        float s0 = 0.f, s1 = 0.f, s2 = 0.f, s3 = 0.f;
        #pragma unroll
        for (int j = 0; j < 16; j++) {
            float4 p;
            p.x = fmaxf(zr[j].x - tau, 0.f); p.x *= p.x;
            p.y = fmaxf(zr[j].y - tau, 0.f); p.y *= p.y;
            p.z = fmaxf(zr[j].z - tau, 0.f); p.z *= p.z;
            p.w = fmaxf(zr[j].w - tau, 0.f); p.w *= p.w;
            s0 += p.x; s1 += p.y; s2 += p.z; s3 += p.w;
            zr[j] = p;
        }
        float Zs = (s0 + s1) + (s2 + s3);
        #pragma unroll
        for (int o = 16; o >= 1; o >>= 1)
            Zs += __shfl_xor_sync(0xffffffffu, Zs, o);
        float invZ = 1.0f / Zs;

        #pragma unroll
        for (int j = 0; j < 16; j++) {
            float4 w;
            w.x = zr[j].x * invZ; w.y = zr[j].y * invZ;
            w.z = zr[j].z * invZ; w.w = zr[j].w * invZ;
            *(float4*)(zrow + (j * 32 + lane) * 4) = w;
        }
    }
    __syncthreads();

    // =========================== Phase 3: PV (f32x2) ===========================
    {
        float* vs = ks;                    // reuse: 128 x 128 floats = 16384 (fits in 16512)
        const int qg3   = warp >> 3;       // 0..1 -> 8 q rows each
        const int kpart = warp & 7;        // 0..7, warp-constant
        const int dg    = lane;            // 0..31 -> 4 d cols

        float4 o[8];
        #pragma unroll
        for (int qi = 0; qi < 8; qi++) o[qi] = make_float4(0.f, 0.f, 0.f, 0.f);
        ull* ov = reinterpret_cast<ull*>(o);   // ov[2*qi], ov[2*qi+1]

        for (int vb = 0; vb < SLEN; vb += 128) {
            __syncthreads();
            #pragma unroll
            for (int r = 0; r < 8; r++)
                ((float4*)vs)[tid + r * 512] =
                    *(const float4*)(Vb + (size_t)vb * DDIM + (tid + r * 512) * 4);
            __syncthreads();

            #pragma unroll
            for (int g = 0; g < 4; g++) {
                int k0 = (g * 8 + kpart) * 4;
                const float* zp = zsh + vb + k0;
                ulonglong2 v0 = *(const ulonglong2*)(vs + (k0 + 0) * DDIM + dg * 4);
                ulonglong2 v1 = *(const ulonglong2*)(vs + (k0 + 1) * DDIM + dg * 4);
                ulonglong2 v2 = *(const ulonglong2*)(vs + (k0 + 2) * DDIM + dg * 4);
                ulonglong2 v3 = *(const ulonglong2*)(vs + (k0 + 3) * DDIM + dg * 4);
                #pragma unroll
                for (int qi = 0; qi < 8; qi++) {
                    float4 w = *(const float4*)(zp + (qg3 * 8 + qi) * ZSTR);  // broadcast
                    ull wx = pack2(w.x), wy = pack2(w.y), wz = pack2(w.z), ww = pack2(w.w);
                    fma2(ov[2*qi],   wx, v0.x); fma2(ov[2*qi+1], wx, v0.y);
                    fma2(ov[2*qi],   wy, v1.x); fma2(ov[2*qi+1], wy, v1.y);
                    fma2(ov[2*qi],   wz, v2.x); fma2(ov[2*qi+1], wz, v2.y);
                    fma2(ov[2*qi],   ww, v3.x); fma2(ov[2*qi+1], ww, v3.y);
                }
            }
        }

        // ---- 3-stage tree reduction of 8 k-partitions via SMEM (float4 slots) ----
        float4* red = (float4*)vs;
        const int base = qg3 * 32 + dg;    // 0..63 (qg3 folded in)

        __syncthreads();
        if (kpart >= 4) {
            int slot = (kpart - 4) * 64 + base;                 // 0..255
            #pragma unroll
            for (int qi = 0; qi < 8; qi++) red[slot + qi * 256] = o[qi];
        }
        __syncthreads();
        if (kpart < 4) {
            int slot = kpart * 64 + base;
            #pragma unroll
            for (int qi = 0; qi < 8; qi++) add4(o[qi], red[slot + qi * 256]);
        }
        __syncthreads();
        if (kpart == 2 || kpart == 3) {
            int slot = (kpart - 2) * 64 + base;                 // 0..127
            #pragma unroll
            for (int qi = 0; qi < 8; qi++) red[slot + qi * 256] = o[qi];
        }
        __syncthreads();
        if (kpart < 2) {
            int slot = kpart * 64 + base;
            #pragma unroll
            for (int qi = 0; qi < 8; qi++) add4(o[qi], red[slot + qi * 256]);
        }
        __syncthreads();
        if (kpart == 1) {
            #pragma unroll
            for (int qi = 0; qi < 8; qi++) red[base + qi * 256] = o[qi];
        }
        __syncthreads();
        if (kpart == 0) {
            #pragma unroll
            for (int qi = 0; qi < 8; qi++) {
                add4(o[qi], red[base + qi * 256]);
                *(float4*)(Ob + (qg3 * 8 + qi) * DDIM + dg * 4) = o[qi];
            }
        }
    }
}

extern "C" void kernel_launch(void* const* d_in, const int* in_sizes, int n_in,
                              void* d_out, int out_size) {
    const float* Q = (const float*)d_in[0];
    const float* K = (const float*)d_in[1];
    const float* V = (const float*)d_in[2];
    float* O = (float*)d_out;

    const int B = in_sizes[0] / (SLEN * DDIM);   // 8
    const size_t smem = (size_t)(TQ * ZSTR + 32 * KSTR2 + 128 * QDSTR) * sizeof(float); // 215,808 B

    cudaFuncSetAttribute(entmax_attn_kernel,
                         cudaFuncAttributeMaxDynamicSharedMemorySize, (int)smem);

    dim3 grid(SLEN / TQ, B);
    entmax_attn_kernel<<<grid, NTHR, smem>>>(Q, K, V, O);
}